// round 6
// baseline (speedup 1.0000x reference)
#include <cuda_runtime.h>
#include <math.h>

#define NAA 5
#define NCC 13
#define NPIX 361
#define MAXOBJ 50
#define NCH 130          /* NA*(13+NC) */
#define TILES 15         /* 3 x-tiles(8) * 5 y-tiles(4) covering 19x19 */
#define NTHR 320         /* 10 warps: (anchor, object-half) */

__device__ double g_accum = 0.0;
__device__ int    g_done  = 0;

__device__ __forceinline__ float sigmoidf_fast(float x) {
    return __fdividef(1.f, 1.f + __expf(-x));
}
__device__ __forceinline__ float sqrt_approx(float x) {
    float r; asm("sqrt.approx.f32 %0, %1;" : "=f"(r) : "f"(x)); return r;
}
__device__ __forceinline__ float ex2_approx(float x) {
    float r; asm("ex2.approx.f32 %0, %1;" : "=f"(r) : "f"(x)); return r;
}

#define INV_CONF0 0.15651764274966568f   /* 1/(e^2-1) */
#define EK1 (-0.036067376f)              /* -0.025 * log2(e) */
#define EK0 (2.88539008f)                /*  2.0   * log2(e) */

__device__ __forceinline__ void corner_acc(float dx, float dy, float& acc) {
    float d2 = fmaf(dy, dy, dx * dx);
    if (d2 < 6400.f)
        acc += ex2_approx(fmaf(sqrt_approx(d2), EK1, EK0)) - 1.f;
}

// grid = (15, nB), block = 320.
// warp w: anchor a = w%5, object half h = w/5 (objects h, h+2, ...).
__global__ void __launch_bounds__(NTHR) fused_kernel(const float* __restrict__ out,
                                                     const float* __restrict__ tgt,
                                                     float* __restrict__ d_out,
                                                     int n_warps) {
    int b    = blockIdx.y;
    int t    = blockIdx.x;
    int tid  = threadIdx.x;
    int w    = tid >> 5;
    int lane = tid & 31;
    int a    = (w < 5) ? w : w - 5;
    int h    = (w < 5) ? 0 : 1;

    __shared__ float  stg[MAXOBJ * 15];   // staged target rows
    __shared__ float4 s4[MAXOBJ * 3];     // scaled corners (2 per float4)
    __shared__ float  stv[MAXOBJ * 12];   // coord targets
    __shared__ float  stconf[MAXOBJ];
    __shared__ int    scls[MAXOBJ];
    __shared__ int    scell[MAXOBJ];
    __shared__ int    swin[NPIX];
    __shared__ int    snv;
    __shared__ float  spart[10 * 32];     // per-warp partial max

    // ---- phase 0: init + coalesced stage of target ----
    if (tid == 0) snv = MAXOBJ;
    for (int c = tid; c < NPIX; c += NTHR) swin[c] = -1;
    {
        const float* src = tgt + (size_t)b * (MAXOBJ * 15);
        #pragma unroll
        for (int k = 0; k < 3; k++) {
            int idx = tid + k * NTHR;
            if (idx < MAXOBJ * 15) stg[idx] = src[idx];
        }
    }
    __syncthreads();

    // ---- phase 1: parse objects from smem ----
    float g[12];
    int gi = 0, gj = 0;
    if (tid < MAXOBJ) {
        const float* row = stg + tid * 15;
        float cls = row[0];
        #pragma unroll
        for (int k = 0; k < 12; k++) g[k] = row[1 + k];
        gi = (int)floorf(g[0] * 19.f);
        gj = (int)floorf(g[1] * 19.f);
        scell[tid] = gj * 19 + gi;
        #pragma unroll
        for (int p = 0; p < 3; p++)
            s4[tid * 3 + p] = make_float4(g[4 * p]     * 640.f, g[4 * p + 1] * 480.f,
                                          g[4 * p + 2] * 640.f, g[4 * p + 3] * 480.f);
        float* tv = stv + tid * 12;
        tv[0] = g[0] * 19.f - (float)gi;
        tv[1] = g[1] * 19.f - (float)gj;
        #pragma unroll
        for (int k = 1; k < 6; k++) {
            tv[2 * k]     = (g[2 * k]     - g[0]) * 19.f;
            tv[2 * k + 1] = (g[2 * k + 1] - g[1]) * 19.f;
        }
        scls[tid] = (int)cls;
        if (g[0] == 0.f) atomicMin(&snv, tid);
    }
    __syncthreads();
    int nv = snv;

    // ---- phase 2: winner table + tconf (anchor-0 conf at object's own cell) ----
    if (tid < nv) {
        atomicMax(&swin[scell[tid]], tid);

        int r = scell[tid];
        const float* base = out + (size_t)b * NCH * NPIX + r;
        float ch[12];
        #pragma unroll
        for (int c = 0; c < 12; c++) ch[c] = base[(size_t)c * NPIX];
        float x0 = sigmoidf_fast(ch[0]);
        float y0 = sigmoidf_fast(ch[1]);
        const float SX = 640.f / 19.f, SY = 480.f / 19.f;
        float px[6], py[6];
        px[0] = (x0 + (float)gi) * SX;
        py[0] = (y0 + (float)gj) * SY;
        #pragma unroll
        for (int k = 1; k < 6; k++) {
            px[k] = fmaf(ch[2 * k],     SX, px[0]);
            py[k] = fmaf(ch[2 * k + 1], SY, py[0]);
        }
        float acc = 0.f;
        #pragma unroll
        for (int c = 0; c < 6; c++)
            corner_acc(g[2 * c] * 640.f - px[c], g[2 * c + 1] * 480.f - py[c], acc);
        stconf[tid] = acc * (INV_CONF0 / 6.f);
    }
    __syncthreads();

    // ---- phase 3: hot loop; (anchor, half) per warp, lane = cell ----
    int tx = t % 3, ty = t / 3;
    int i = tx * 8 + (lane & 7);
    int j = ty * 4 + (lane >> 3);
    bool active = (i < 19) && (j < 19);
    int r = j * 19 + i;

    const float* base = out + ((size_t)b * NCH + a * 26) * NPIX + r;
    float ch[12];
    float x0 = 0.f, y0 = 0.f;
    float px[6], py[6];
    if (active) {
        #pragma unroll
        for (int c = 0; c < 12; c++) ch[c] = base[(size_t)c * NPIX];
        x0 = sigmoidf_fast(ch[0]);
        y0 = sigmoidf_fast(ch[1]);
        const float SX = 640.f / 19.f, SY = 480.f / 19.f;
        px[0] = (x0 + (float)i) * SX;
        py[0] = (y0 + (float)j) * SY;
        #pragma unroll
        for (int k = 1; k < 6; k++) {
            px[k] = fmaf(ch[2 * k],     SX, px[0]);
            py[k] = fmaf(ch[2 * k + 1], SY, py[0]);
        }
    } else {
        #pragma unroll
        for (int k = 0; k < 6; k++) { px[k] = 1e9f; py[k] = 1e9f; }
    }

    float m = 0.f;
    for (int q = h; q < nv; q += 2) {
        const float4* op = s4 + q * 3;
        float acc = 0.f;
        #pragma unroll
        for (int p = 0; p < 3; p++) {
            float4 v = op[p];
            corner_acc(v.x - px[2 * p],     v.y - py[2 * p],     acc);
            corner_acc(v.z - px[2 * p + 1], v.w - py[2 * p + 1], acc);
        }
        m = fmaxf(m, acc);
    }
    spart[w * 32 + lane] = m;
    __syncthreads();

    // ---- epilogue: low warps combine + compute losses ----
    if (w >= 5) return;

    float lsum = 0.f;
    if (active) {
        m = fmaxf(spart[w * 32 + lane], spart[(w + 5) * 32 + lane]);
        m *= (INV_CONF0 / 6.f);

        float conf = sigmoidf_fast(base[(size_t)12 * NPIX]);
        float mask = (m < 0.4f) ? 1.f : 0.f;
        float tc = 0.f;

        if (a == 0) {
            int win = swin[r];
            if (win >= 0) {
                mask = 5.f;   // OBJECT_SCALE
                tc = stconf[win];

                const float* tv = stv + win * 12;
                float d0 = x0 - tv[0];
                float d1 = y0 - tv[1];
                float cs = fmaf(d1, d1, d0 * d0);
                #pragma unroll
                for (int k = 2; k < 12; k++) {
                    float d = ch[k] - tv[k];
                    cs = fmaf(d, d, cs);
                }
                lsum += 0.5f * cs;

                const float* cbase = base + (size_t)13 * NPIX;
                float lg[NCC];
                float mx = -1e30f;
                #pragma unroll
                for (int c = 0; c < NCC; c++) {
                    lg[c] = cbase[(size_t)c * NPIX];
                    mx = fmaxf(mx, lg[c]);
                }
                float se = 0.f;
                #pragma unroll
                for (int c = 0; c < NCC; c++) se += __expf(lg[c] - mx);
                lsum += mx + __logf(se) - lg[scls[win]];
            }
        }
        float cd = conf - tc;
        lsum += 0.5f * mask * cd * cd;
    }

    #pragma unroll
    for (int off = 16; off > 0; off >>= 1)
        lsum += __shfl_down_sync(0xffffffffu, lsum, off);
    if (lane == 0) {
        atomicAdd(&g_accum, (double)lsum);
        __threadfence();
        int old = atomicAdd(&g_done, 1);
        if (old == n_warps - 1) {
            d_out[0] = (float)g_accum;
            g_accum = 0.0;
            g_done = 0;
        }
    }
}

extern "C" void kernel_launch(void* const* d_in, const int* in_sizes, int n_in,
                              void* d_out, int out_size) {
    const float* out = (const float*)d_in[0];
    const float* tgt = (const float*)d_in[1];
    int nB = in_sizes[0] / (NCH * NPIX);

    dim3 grid(TILES, nB);
    fused_kernel<<<grid, NTHR>>>(out, tgt, (float*)d_out, TILES * nB * NAA);
}